// round 7
// baseline (speedup 1.0000x reference)
#include <cuda_runtime.h>
#include <stdint.h>

#define BB 16
#define NN 2048
#define KK 20
#define ROWS (BB * NN)
#define LSTRIDE 512          // adjacency entries per row (20 direct + transpose)
#define TCAP (LSTRIDE - KK)
#define PREF 1.79985f        // 1.8 - 1e-4 with margin

// ---- scratch (static __device__ — no allocations allowed) ----
__device__ unsigned long long g_list[(size_t)ROWS * LSTRIDE]; // (col<<32)|bits(v)
__device__ int   g_tcnt[ROWS];   // transpose counters (zero-init; writer re-zeroes)
__device__ float g_dinv[ROWS];

// ---------------------------------------------------------------------------
// One block per row. Streams A (two float4/thread). Hierarchical filter:
// max(float4) tested once; per-element noise fetch only for vectors that can
// clear the 1.8 doped threshold. Exact top-K via parallel rank-count with
// jax's lowest-index tie-break (key = doped_bits<<11 | (2047-col));
// accept-all fallback if < K survive. Winners reload relu value from A.
__global__ __launch_bounds__(256) void k_topk(const float* __restrict__ A,
                                              const float* __restrict__ Noise) {
    const int row  = blockIdx.x;       // b * NN + i
    const int tid  = threadIdx.x;
    const int b    = row >> 11;
    const size_t base = (size_t)row << 11;

    __shared__ unsigned long long sK[NN];
    __shared__ uint32_t s_cnt, s_kslot;
    if (tid == 0) { s_cnt = 0; s_kslot = 0; }
    __syncthreads();

    const float4* a4 = (const float4*)(A + base);
    float4 av  = a4[tid];
    float4 av2 = a4[256 + tid];
    const uint32_t TH = __float_as_uint(1.8f);

    // ---- hierarchical candidate filter ----
    {
        float m1 = fmaxf(fmaxf(av.x, av.y), fmaxf(av.z, av.w));
        if (m1 > PREF) {
            float f[4] = {av.x, av.y, av.z, av.w};
#pragma unroll
            for (int e = 0; e < 4; e++) {
                if (f[e] > PREF) {
                    int col = tid * 4 + e;
                    float n = __ldg(Noise + base + col);
                    float d = __fadd_rn(f[e], __fmul_rn(n, 1e-4f));
                    uint32_t dbits = __float_as_uint(d);
                    if (dbits > TH) {
                        uint32_t p = atomicAdd(&s_cnt, 1u);
                        sK[p] = ((unsigned long long)dbits << 11)
                              | (unsigned long long)(2047 - col);
                    }
                }
            }
        }
        float m2 = fmaxf(fmaxf(av2.x, av2.y), fmaxf(av2.z, av2.w));
        if (m2 > PREF) {
            float f[4] = {av2.x, av2.y, av2.z, av2.w};
#pragma unroll
            for (int e = 0; e < 4; e++) {
                if (f[e] > PREF) {
                    int col = 1024 + tid * 4 + e;
                    float n = __ldg(Noise + base + col);
                    float d = __fadd_rn(f[e], __fmul_rn(n, 1e-4f));
                    uint32_t dbits = __float_as_uint(d);
                    if (dbits > TH) {
                        uint32_t p = atomicAdd(&s_cnt, 1u);
                        sK[p] = ((unsigned long long)dbits << 11)
                              | (unsigned long long)(2047 - col);
                    }
                }
            }
        }
    }
    __syncthreads();
    uint32_t M = s_cnt;

    if (M < KK) {
        // rare exact fallback: rebuild all 2048 keys (noise row loaded in full)
        const float4* n4 = (const float4*)(Noise + base);
        float4 nv  = n4[tid];
        float4 nv2 = n4[256 + tid];
        float f[8]  = {av.x, av.y, av.z, av.w, av2.x, av2.y, av2.z, av2.w};
        float no[8] = {nv.x, nv.y, nv.z, nv.w, nv2.x, nv2.y, nv2.z, nv2.w};
#pragma unroll
        for (int e = 0; e < 8; e++) {
            int col = (e < 4) ? (tid * 4 + e) : (1024 + tid * 4 + (e - 4));
            float r = fmaxf(f[e], 0.0f);
            float d = __fadd_rn(r, __fmul_rn(no[e], 1e-4f));
            sK[col] = ((unsigned long long)__float_as_uint(d) << 11)
                    | (unsigned long long)(2047 - col);
        }
        __syncthreads();
        M = NN;
    }

    // ---- parallel rank-count; keys distinct -> exactly KK winners ----
    for (uint32_t i = tid; i < M; i += 256) {
        const unsigned long long key = sK[i];
        uint32_t rank = 0;
        for (uint32_t q = 0; q < M; q++)
            rank += (sK[q] > key);
        if (rank < KK) {
            int   col = 2047 - (int)(key & 2047u);
            float r   = fmaxf(__ldg(A + base + col), 0.0f);  // exact relu value
            unsigned long long entry =
                ((unsigned long long)col << 32)
              | (unsigned long long)__float_as_uint(r);
            uint32_t p = atomicAdd(&s_kslot, 1u);
            g_list[(size_t)row * LSTRIDE + p] = entry;        // direct slot
            int jrow = b * NN + col;                          // transpose entry
            uint32_t t = atomicAdd((unsigned int*)&g_tcnt[jrow], 1u);
            if (t < TCAP)
                g_list[(size_t)jrow * LSTRIDE + KK + t] =
                    ((unsigned long long)(row & 2047) << 32)
                  | (unsigned long long)__float_as_uint(r);
        }
    }
}

// ---------------------------------------------------------------------------
// Warp per row: d_i = 1 + 0.5 * sum(list values); self-loops double-count
// exactly as rowsum+colsum does. dinv = rsqrt(d_i).
__global__ __launch_bounds__(256) void k_deg() {
    int warp = (blockIdx.x * 256 + threadIdx.x) >> 5;
    int lane = threadIdx.x & 31;
    if (warp >= ROWS) return;
    int tc = g_tcnt[warp]; if (tc > TCAP) tc = TCAP;
    int n  = KK + tc;
    float s = 0.0f;
    const unsigned long long* lst = g_list + (size_t)warp * LSTRIDE;
    for (int i = lane; i < n; i += 32)
        s += __uint_as_float((uint32_t)lst[i]);
#pragma unroll
    for (int off = 16; off; off >>= 1)
        s += __shfl_down_sync(0xffffffffu, s, off);
    if (lane == 0)
        g_dinv[warp] = rsqrtf(fmaf(0.5f, s, 1.0f));
}

// ---------------------------------------------------------------------------
// Block per row: stage batch dinv in smem, zero smem row, scatter weighted
// entries + diagonal, stream the dense row out evict-first; re-zero counter.
__global__ __launch_bounds__(256) void k_writer(float* __restrict__ out) {
    const int row = blockIdx.x;
    const int tid = threadIdx.x;
    const int b   = row >> 11;

    __shared__ float srow[NN];
    __shared__ float sdinv[NN];
    float4* s4 = (float4*)srow;
    s4[tid]       = make_float4(0.f, 0.f, 0.f, 0.f);
    s4[256 + tid] = make_float4(0.f, 0.f, 0.f, 0.f);
    const float4* dv4 = (const float4*)(g_dinv + ((size_t)b << 11));
    ((float4*)sdinv)[tid]       = dv4[tid];
    ((float4*)sdinv)[256 + tid] = dv4[256 + tid];

    int tc = g_tcnt[row]; if (tc > TCAP) tc = TCAP;
    const int n = KK + tc;
    __syncthreads();

    const float di = sdinv[row & 2047];
    const unsigned long long* lst = g_list + (size_t)row * LSTRIDE;
    for (int t = tid; t < n; t += 256) {
        unsigned long long e = lst[t];
        int   col = (int)(e >> 32);
        float v   = __uint_as_float((uint32_t)e);
        float w   = 0.5f * v * di * sdinv[col];
        atomicAdd(&srow[col], w);
    }
    if (tid == 0) atomicAdd(&srow[row & 2047], di * di);
    __syncthreads();

    float4* o4 = (float4*)(out + ((size_t)row << 11));
    __stcs(&o4[tid],       s4[tid]);
    __stcs(&o4[256 + tid], s4[256 + tid]);

    if (tid == 0) g_tcnt[row] = 0;   // next call sees zeroed counters
}

// ---------------------------------------------------------------------------
extern "C" void kernel_launch(void* const* d_in, const int* in_sizes, int n_in,
                              void* d_out, int out_size) {
    const float* A     = (const float*)d_in[0];
    const float* Noise = (const float*)d_in[1];
    float* out = (float*)d_out;

    k_topk  <<<ROWS, 256>>>(A, Noise);
    k_deg   <<<(ROWS * 32 + 255) / 256, 256>>>();
    k_writer<<<ROWS, 256>>>(out);
}

// round 8
// speedup vs baseline: 1.1507x; 1.1507x over previous
#include <cuda_runtime.h>
#include <stdint.h>

#define BB 16
#define NN 2048
#define KK 20
#define ROWS (BB * NN)
#define LSTRIDE 512          // adjacency entries per row (20 direct + transpose)
#define TCAP (LSTRIDE - KK)
#define THRESH 2.0f
#define PREF 1.99985f        // 2.0 - 1e-4 with margin

// ---- scratch (static __device__ — no allocations allowed) ----
__device__ unsigned long long g_list[(size_t)ROWS * LSTRIDE]; // (col<<32)|bits(v)
__device__ int   g_tcnt[ROWS];   // transpose counters (zero-init; writer re-zeroes)
__device__ float g_dinv[ROWS];

// ---------------------------------------------------------------------------
// One block per row. Streams A (two float4/thread); noise fetched only for
// elements whose relu could clear the 2.0 doped threshold (~2.3%). Exact
// top-K via parallel rank-count with jax's lowest-index tie-break
// (key = doped_bits<<11 | (2047-col)); accept-all fallback if < K survive.
__global__ __launch_bounds__(256) void k_topk(const float* __restrict__ A,
                                              const float* __restrict__ Noise) {
    const int row  = blockIdx.x;       // b * NN + i
    const int tid  = threadIdx.x;
    const int b    = row >> 11;
    const size_t base = (size_t)row << 11;

    __shared__ unsigned long long sK[NN];
    __shared__ float    sV[NN];
    __shared__ uint32_t s_cnt, s_kslot;
    if (tid == 0) { s_cnt = 0; s_kslot = 0; }
    __syncthreads();

    const float4* a4 = (const float4*)(A + base);
    float4 av  = a4[tid];
    float4 av2 = a4[256 + tid];
    const uint32_t TH = __float_as_uint(THRESH);

    {
        float f[8] = {av.x, av.y, av.z, av.w, av2.x, av2.y, av2.z, av2.w};
#pragma unroll
        for (int e = 0; e < 8; e++) {
            if (f[e] > PREF) {
                int col = (e < 4) ? (tid * 4 + e) : (1024 + tid * 4 + (e - 4));
                float n = __ldg(Noise + base + col);
                float d = __fadd_rn(f[e], __fmul_rn(n, 1e-4f));
                uint32_t dbits = __float_as_uint(d);
                if (dbits > TH) {
                    uint32_t p = atomicAdd(&s_cnt, 1u);
                    sK[p] = ((unsigned long long)dbits << 11)
                          | (unsigned long long)(2047 - col);
                    sV[p] = f[e];
                }
            }
        }
    }
    __syncthreads();
    uint32_t M = s_cnt;

    if (M < KK) {
        // rare exact fallback: rebuild all 2048 keys (full noise row)
        const float4* n4 = (const float4*)(Noise + base);
        float4 nv  = n4[tid];
        float4 nv2 = n4[256 + tid];
        float f[8]  = {av.x, av.y, av.z, av.w, av2.x, av2.y, av2.z, av2.w};
        float no[8] = {nv.x, nv.y, nv.z, nv.w, nv2.x, nv2.y, nv2.z, nv2.w};
#pragma unroll
        for (int e = 0; e < 8; e++) {
            int col = (e < 4) ? (tid * 4 + e) : (1024 + tid * 4 + (e - 4));
            float r = fmaxf(f[e], 0.0f);
            float d = __fadd_rn(r, __fmul_rn(no[e], 1e-4f));
            sK[col] = ((unsigned long long)__float_as_uint(d) << 11)
                    | (unsigned long long)(2047 - col);
            sV[col] = r;
        }
        __syncthreads();
        M = NN;
    }

    // ---- parallel rank-count; keys distinct -> exactly KK winners ----
    for (uint32_t i = tid; i < M; i += 256) {
        const unsigned long long key = sK[i];
        uint32_t rank = 0;
#pragma unroll 4
        for (uint32_t q = 0; q < M; q++)
            rank += (sK[q] > key);
        if (rank < KK) {
            int   col = 2047 - (int)(key & 2047u);
            float r   = sV[i];
            unsigned long long entry =
                ((unsigned long long)col << 32)
              | (unsigned long long)__float_as_uint(r);
            uint32_t p = atomicAdd(&s_kslot, 1u);
            g_list[(size_t)row * LSTRIDE + p] = entry;        // direct slot
            int jrow = b * NN + col;                          // transpose entry
            uint32_t t = atomicAdd((unsigned int*)&g_tcnt[jrow], 1u);
            if (t < TCAP)
                g_list[(size_t)jrow * LSTRIDE + KK + t] =
                    ((unsigned long long)(row & 2047) << 32)
                  | (unsigned long long)__float_as_uint(r);
        }
    }
}

// ---------------------------------------------------------------------------
// Warp per row: d_i = 1 + 0.5 * sum(list values); dinv = rsqrt(d_i).
__global__ __launch_bounds__(256) void k_deg() {
    int warp = (blockIdx.x * 256 + threadIdx.x) >> 5;
    int lane = threadIdx.x & 31;
    if (warp >= ROWS) return;
    int tc = g_tcnt[warp]; if (tc > TCAP) tc = TCAP;
    int n  = KK + tc;
    float s = 0.0f;
    const unsigned long long* lst = g_list + (size_t)warp * LSTRIDE;
    for (int i = lane; i < n; i += 32)
        s += __uint_as_float((uint32_t)lst[i]);
#pragma unroll
    for (int off = 16; off; off >>= 1)
        s += __shfl_down_sync(0xffffffffu, s, off);
    if (lane == 0)
        g_dinv[warp] = rsqrtf(fmaf(0.5f, s, 1.0f));
}

// ---------------------------------------------------------------------------
// Block per row: zero smem row, scatter weighted entries + diagonal (dinv via
// L2-hot __ldg), stream dense row out evict-first; re-zero counter.
__global__ __launch_bounds__(256) void k_writer(float* __restrict__ out) {
    const int row = blockIdx.x;
    const int tid = threadIdx.x;
    const int b   = row >> 11;

    __shared__ float srow[NN];
    float4* s4 = (float4*)srow;
    s4[tid]       = make_float4(0.f, 0.f, 0.f, 0.f);
    s4[256 + tid] = make_float4(0.f, 0.f, 0.f, 0.f);

    const float di = g_dinv[row];
    int tc = g_tcnt[row]; if (tc > TCAP) tc = TCAP;
    const int n = KK + tc;
    __syncthreads();

    const unsigned long long* lst = g_list + (size_t)row * LSTRIDE;
    for (int t = tid; t < n; t += 256) {
        unsigned long long e = lst[t];
        int   col = (int)(e >> 32);
        float v   = __uint_as_float((uint32_t)e);
        float w   = 0.5f * v * di * __ldg(&g_dinv[b * NN + col]);
        atomicAdd(&srow[col], w);
    }
    if (tid == 0) atomicAdd(&srow[row & 2047], di * di);
    __syncthreads();

    float4* o4 = (float4*)(out + ((size_t)row << 11));
    __stcs(&o4[tid],       s4[tid]);
    __stcs(&o4[256 + tid], s4[256 + tid]);

    if (tid == 0) g_tcnt[row] = 0;   // next call sees zeroed counters
}

// ---------------------------------------------------------------------------
extern "C" void kernel_launch(void* const* d_in, const int* in_sizes, int n_in,
                              void* d_out, int out_size) {
    const float* A     = (const float*)d_in[0];
    const float* Noise = (const float*)d_in[1];
    float* out = (float*)d_out;

    k_topk  <<<ROWS, 256>>>(A, Noise);
    k_deg   <<<(ROWS * 32 + 255) / 256, 256>>>();
    k_writer<<<ROWS, 256>>>(out);
}

// round 9
// speedup vs baseline: 1.2380x; 1.0759x over previous
#include <cuda_runtime.h>
#include <stdint.h>

#define BB 16
#define NN 2048
#define KK 20
#define ROWS (BB * NN)
#define LSTRIDE 512          // adjacency entries per row (20 direct + transpose)
#define TCAP (LSTRIDE - KK)
#define TH1 2.2f
#define PREF1 2.19985f       // 2.2 - 1e-4 with margin
#define TH2 1.8f
#define PREF2 1.79985f

// ---- scratch (static __device__ — no allocations allowed) ----
__device__ unsigned long long g_list[(size_t)ROWS * LSTRIDE]; // (col<<32)|bits(v)
__device__ int   g_tcnt[ROWS];   // transpose counters (zero-init; writer re-zeroes)
__device__ float g_dinv[ROWS];

// ---------------------------------------------------------------------------
// One block per row. Streams A (two float4/thread); noise fetched only for
// elements whose relu could clear the doped threshold. Tiered thresholds:
// 2.2 (M~28) -> 1.8 re-filter from registers (~4.5% of rows) -> full rebuild
// (astronomically rare). Exact top-K via parallel rank-count with jax's
// lowest-index tie-break (key = doped_bits<<11 | (2047-col)).
__global__ __launch_bounds__(256) void k_topk(const float* __restrict__ A,
                                              const float* __restrict__ Noise) {
    const int row  = blockIdx.x;       // b * NN + i
    const int tid  = threadIdx.x;
    const int b    = row >> 11;
    const size_t base = (size_t)row << 11;

    __shared__ unsigned long long sK[NN];
    __shared__ float    sV[NN];
    __shared__ uint32_t s_cnt, s_kslot;
    if (tid == 0) { s_cnt = 0; s_kslot = 0; }
    __syncthreads();

    const float4* a4 = (const float4*)(A + base);
    float4 av  = a4[tid];
    float4 av2 = a4[256 + tid];
    float f[8] = {av.x, av.y, av.z, av.w, av2.x, av2.y, av2.z, av2.w};

    // ---- tier 1: threshold 2.2 ----
    {
        const uint32_t TH = __float_as_uint(TH1);
#pragma unroll
        for (int e = 0; e < 8; e++) {
            if (f[e] > PREF1) {
                int col = (e < 4) ? (tid * 4 + e) : (1024 + tid * 4 + (e - 4));
                float n = __ldg(Noise + base + col);
                float d = __fadd_rn(f[e], __fmul_rn(n, 1e-4f));
                uint32_t dbits = __float_as_uint(d);
                if (dbits > TH) {
                    uint32_t p = atomicAdd(&s_cnt, 1u);
                    sK[p] = ((unsigned long long)dbits << 11)
                          | (unsigned long long)(2047 - col);
                    sV[p] = f[e];
                }
            }
        }
    }
    __syncthreads();
    uint32_t M = s_cnt;

    if (M < KK) {
        // ---- tier 2: re-filter at 1.8 from registers (A not re-read) ----
        __syncthreads();
        if (tid == 0) s_cnt = 0;
        __syncthreads();
        const uint32_t TH = __float_as_uint(TH2);
#pragma unroll
        for (int e = 0; e < 8; e++) {
            if (f[e] > PREF2) {
                int col = (e < 4) ? (tid * 4 + e) : (1024 + tid * 4 + (e - 4));
                float n = __ldg(Noise + base + col);
                float d = __fadd_rn(f[e], __fmul_rn(n, 1e-4f));
                uint32_t dbits = __float_as_uint(d);
                if (dbits > TH) {
                    uint32_t p = atomicAdd(&s_cnt, 1u);
                    sK[p] = ((unsigned long long)dbits << 11)
                          | (unsigned long long)(2047 - col);
                    sV[p] = f[e];
                }
            }
        }
        __syncthreads();
        M = s_cnt;

        if (M < KK) {
            // ---- tier 3: exact full rebuild (all 2048 keys) ----
            const float4* n4 = (const float4*)(Noise + base);
            float4 nv  = n4[tid];
            float4 nv2 = n4[256 + tid];
            float no[8] = {nv.x, nv.y, nv.z, nv.w, nv2.x, nv2.y, nv2.z, nv2.w};
#pragma unroll
            for (int e = 0; e < 8; e++) {
                int col = (e < 4) ? (tid * 4 + e) : (1024 + tid * 4 + (e - 4));
                float r = fmaxf(f[e], 0.0f);
                float d = __fadd_rn(r, __fmul_rn(no[e], 1e-4f));
                sK[col] = ((unsigned long long)__float_as_uint(d) << 11)
                        | (unsigned long long)(2047 - col);
                sV[col] = r;
            }
            __syncthreads();
            M = NN;
        }
    }

    // ---- parallel rank-count; keys distinct -> exactly KK winners ----
    for (uint32_t i = tid; i < M; i += 256) {
        const unsigned long long key = sK[i];
        uint32_t rank = 0;
#pragma unroll 4
        for (uint32_t q = 0; q < M; q++)
            rank += (sK[q] > key);
        if (rank < KK) {
            int   col = 2047 - (int)(key & 2047u);
            float r   = sV[i];
            unsigned long long entry =
                ((unsigned long long)col << 32)
              | (unsigned long long)__float_as_uint(r);
            uint32_t p = atomicAdd(&s_kslot, 1u);
            g_list[(size_t)row * LSTRIDE + p] = entry;        // direct slot
            int jrow = b * NN + col;                          // transpose entry
            uint32_t t = atomicAdd((unsigned int*)&g_tcnt[jrow], 1u);
            if (t < TCAP)
                g_list[(size_t)jrow * LSTRIDE + KK + t] =
                    ((unsigned long long)(row & 2047) << 32)
                  | (unsigned long long)__float_as_uint(r);
        }
    }
}

// ---------------------------------------------------------------------------
// Warp per row: d_i = 1 + 0.5 * sum(list values); dinv = rsqrt(d_i).
__global__ __launch_bounds__(256) void k_deg() {
    int warp = (blockIdx.x * 256 + threadIdx.x) >> 5;
    int lane = threadIdx.x & 31;
    if (warp >= ROWS) return;
    int tc = g_tcnt[warp]; if (tc > TCAP) tc = TCAP;
    int n  = KK + tc;
    float s = 0.0f;
    const unsigned long long* lst = g_list + (size_t)warp * LSTRIDE;
    for (int i = lane; i < n; i += 32)
        s += __uint_as_float((uint32_t)lst[i]);
#pragma unroll
    for (int off = 16; off; off >>= 1)
        s += __shfl_down_sync(0xffffffffu, s, off);
    if (lane == 0)
        g_dinv[warp] = rsqrtf(fmaf(0.5f, s, 1.0f));
}

// ---------------------------------------------------------------------------
// Block per row: zero smem row, scatter weighted entries + diagonal (dinv via
// L2-hot __ldg), stream dense row out evict-first; re-zero counter.
__global__ __launch_bounds__(256) void k_writer(float* __restrict__ out) {
    const int row = blockIdx.x;
    const int tid = threadIdx.x;
    const int b   = row >> 11;

    __shared__ float srow[NN];
    float4* s4 = (float4*)srow;
    s4[tid]       = make_float4(0.f, 0.f, 0.f, 0.f);
    s4[256 + tid] = make_float4(0.f, 0.f, 0.f, 0.f);

    const float di = g_dinv[row];
    int tc = g_tcnt[row]; if (tc > TCAP) tc = TCAP;
    const int n = KK + tc;
    __syncthreads();

    const unsigned long long* lst = g_list + (size_t)row * LSTRIDE;
    for (int t = tid; t < n; t += 256) {
        unsigned long long e = lst[t];
        int   col = (int)(e >> 32);
        float v   = __uint_as_float((uint32_t)e);
        float w   = 0.5f * v * di * __ldg(&g_dinv[b * NN + col]);
        atomicAdd(&srow[col], w);
    }
    if (tid == 0) atomicAdd(&srow[row & 2047], di * di);
    __syncthreads();

    float4* o4 = (float4*)(out + ((size_t)row << 11));
    __stcs(&o4[tid],       s4[tid]);
    __stcs(&o4[256 + tid], s4[256 + tid]);

    if (tid == 0) g_tcnt[row] = 0;   // next call sees zeroed counters
}

// ---------------------------------------------------------------------------
extern "C" void kernel_launch(void* const* d_in, const int* in_sizes, int n_in,
                              void* d_out, int out_size) {
    const float* A     = (const float*)d_in[0];
    const float* Noise = (const float*)d_in[1];
    float* out = (float*)d_out;

    k_topk  <<<ROWS, 256>>>(A, Noise);
    k_deg   <<<(ROWS * 32 + 255) / 256, 256>>>();
    k_writer<<<ROWS, 256>>>(out);
}